// round 2
// baseline (speedup 1.0000x reference)
#include <cuda_runtime.h>

// DeEmphasis: y[n] = x[n] + ALPHA*y[n-1], zero init, rows of 960000 fp32.
//
// R2: warp-autonomous spans, zero shared memory.
// Each warp owns payload P=7680 + halo H=256 (alpha^256 ~ 8.5e-19, below fp32
// eps -> bitwise-independent chunks). Per 128-element group: lane holds one
// float4 (coalesced), 3-FMA local scan, 5-step warp Kogge-Stone affine scan
// over lane totals (coef alpha^4), recompute 4 outputs from true entering
// state, store float4. Inter-group carry is one FMA (alpha^128 * c + wtot);
// the shfl scans of the 4x-unrolled groups are independent -> ILP + MLP 4.

#define ALPHA 0.85f

static constexpr int ROWLEN  = 960000;
static constexpr int P       = 7680;           // payload per warp
static constexpr int H       = 256;            // halo = 2 groups of 128
static constexpr int SPANS   = ROWLEN / P;     // 125 spans per row
static constexpr int WPB     = 4;              // warps per block
static constexpr int THREADS = WPB * 32;       // 128
static constexpr int MAIN_ITERS = P / 128;     // 60 (divisible by 4)

// compile-time alpha^n (double accumulation, rounded once)
__host__ __device__ constexpr float apow(int n) {
    double r = 1.0;
    for (int i = 0; i < n; i++) r *= (double)ALPHA;
    return (float)r;
}

// Process one 128-element group (4 consecutive elems per lane).
// c: warp-entering filter state (updated). Returns the 4 outputs.
__device__ __forceinline__ float4 proc128(float4 v, float AL, float& c, int lane)
{
    const float A    = ALPHA;
    const float A4   = apow(4);
    const float A128 = apow(128);

    // local inclusive scan of the lane's 4 elements (zero entering)
    float l1 = fmaf(A, v.x, v.y);
    float l2 = fmaf(A, l1, v.z);
    float l3 = fmaf(A, l2, v.w);

    // warp Kogge-Stone affine scan over lane totals, per-lane coef alpha^4
    float s = l3, cp = A4;
    #pragma unroll
    for (int d = 1; d < 32; d <<= 1) {
        float u = __shfl_up_sync(0xffffffffu, s, d);
        if (lane >= d) s = fmaf(cp, u, s);
        cp *= cp;
    }
    float wtot = __shfl_sync(0xffffffffu, s, 31);     // warp total (zero entry)
    float e    = __shfl_up_sync(0xffffffffu, s, 1);   // exclusive: state entering my group
    if (lane == 0) e = 0.0f;

    // true entering state for this lane's 4-group: e + alpha^(4*lane) * c
    float enter = fmaf(AL, c, e);

    float4 o;
    o.x = fmaf(A, enter, v.x);
    o.y = fmaf(A, o.x,  v.y);
    o.z = fmaf(A, o.y,  v.z);
    o.w = fmaf(A, o.z,  v.w);

    c = fmaf(A128, c, wtot);    // carry into next 128-group
    return o;
}

__global__ void __launch_bounds__(THREADS, 10)
deemph_kernel(const float* __restrict__ x, float* __restrict__ y, int nwarps)
{
    const int gw = blockIdx.x * WPB + (threadIdx.x >> 5);
    if (gw >= nwarps) return;
    const int lane = threadIdx.x & 31;
    const int row  = gw / SPANS;
    const int span = gw - row * SPANS;

    // per-lane constant alpha^(4*lane) via 5 conditional multiplies
    float AL = 1.0f;
    if (lane & 1)  AL *= apow(4);
    if (lane & 2)  AL *= apow(8);
    if (lane & 4)  AL *= apow(16);
    if (lane & 8)  AL *= apow(32);
    if (lane & 16) AL *= apow(64);

    const float* px = x + row * ROWLEN + span * P + lane * 4;
    float*       py = y + row * ROWLEN + span * P + lane * 4;

    float c = 0.0f;

    // halo warm-up: 2 groups before the payload (span 0 has true zero history)
    if (span > 0) {
        float4 h0 = __ldcs((const float4*)(px - H));
        float4 h1 = __ldcs((const float4*)(px - H + 128));
        (void)proc128(h0, AL, c, lane);
        (void)proc128(h1, AL, c, lane);
    }

    // main: 60 groups, 4-wide pipelined (independent loads + shfl chains)
    #pragma unroll 1
    for (int k = 0; k < MAIN_ITERS; k += 4) {
        const float* p = px + k * 128;
        float4 v0 = __ldcs((const float4*)(p));
        float4 v1 = __ldcs((const float4*)(p + 128));
        float4 v2 = __ldcs((const float4*)(p + 256));
        float4 v3 = __ldcs((const float4*)(p + 384));

        float4 o0 = proc128(v0, AL, c, lane);
        float4 o1 = proc128(v1, AL, c, lane);
        float4 o2 = proc128(v2, AL, c, lane);
        float4 o3 = proc128(v3, AL, c, lane);

        float* q = py + k * 128;
        __stcs((float4*)(q),       o0);
        __stcs((float4*)(q + 128), o1);
        __stcs((float4*)(q + 256), o2);
        __stcs((float4*)(q + 384), o3);
    }
}

extern "C" void kernel_launch(void* const* d_in, const int* in_sizes, int n_in,
                              void* d_out, int out_size)
{
    const float* x = (const float*)d_in[0];
    float*       y = (float*)d_out;

    const int n      = in_sizes[0];        // 61,440,000
    const int rows   = n / ROWLEN;         // 64
    const int nwarps = rows * SPANS;       // 8000
    const int blocks = (nwarps + WPB - 1) / WPB;   // 2000

    deemph_kernel<<<blocks, THREADS>>>(x, y, nwarps);
}